// round 17
// baseline (speedup 1.0000x reference)
#include <cuda_runtime.h>
#include <math.h>

// Problem constants (fixed shapes per reference)
#define B_EV   20
#define V_EV   3000
#define KNN_K  40
#define FIN    64
#define PROP   64
#define DIM    4
#define FOUT   128
#define NHITS  (B_EV * V_EV)        // 60000
#define AIN    (2 * PROP + FIN)     // 192

typedef unsigned long long ull;

// Scratch (device globals; no allocations allowed)
__device__ float g_feat[NHITS * PROP];       // relu(x@W_prop+b) [N,64]
__device__ float g_coords[NHITS * DIM];      // x@W_sp+b         [N,4] (AoS)
__device__ __align__(16) float g_cx[NHITS];  // SoA coords + norm
__device__ __align__(16) float g_cy[NHITS];
__device__ __align__(16) float g_cz[NHITS];
__device__ __align__(16) float g_cw[NHITS];
__device__ __align__(16) float g_cn[NHITS];
__device__ int   g_nidx[NHITS * KNN_K];      // global neighbor idx
__device__ float g_dist[NHITS * KNN_K];      // clamped distsq
__device__ float g_a[(size_t)NHITS * AIN];   // GEMM input [N,192]
__device__ int   g_sink;                     // nop-kernel sink

// ---------------------------------------------------------------------------
// K1: coordinates = x@W_sp + b_sp ; feat = relu(x@W_prop + b_prop)
// ---------------------------------------------------------------------------
__global__ __launch_bounds__(256)
void k_transform(const float* __restrict__ x,
                 const float* __restrict__ Wp, const float* __restrict__ bp,
                 const float* __restrict__ Ws, const float* __restrict__ bs,
                 float* __restrict__ coords_out)  // may be null
{
    __shared__ float xs[4][FIN];
    int h = threadIdx.x >> 6;
    int j = threadIdx.x & 63;
    int hit = blockIdx.x * 4 + h;
    if (hit < NHITS) xs[h][j] = x[hit * FIN + j];
    __syncthreads();
    if (hit >= NHITS) return;

    float acc = bp[j];
#pragma unroll
    for (int i = 0; i < FIN; i++)
        acc += xs[h][i] * Wp[i * PROP + j];
    g_feat[hit * PROP + j] = fmaxf(acc, 0.0f);

    if (j < DIM) {
        float c = bs[j];
#pragma unroll
        for (int i = 0; i < FIN; i++)
            c += xs[h][i] * Ws[i * DIM + j];
        g_coords[hit * DIM + j] = c;
        if (coords_out) coords_out[hit * DIM + j] = c;
    }
}

// AoS -> SoA + per-hit norm
__global__ __launch_bounds__(256)
void k_soa()
{
    int i = blockIdx.x * 256 + threadIdx.x;
    if (i >= NHITS) return;
    float4 c = *(const float4*)&g_coords[(size_t)i * 4];
    g_cx[i] = c.x; g_cy[i] = c.y; g_cz[i] = c.z; g_cw[i] = c.w;
    g_cn[i] = ((c.x * c.x + c.y * c.y) + c.z * c.z) + c.w * c.w;
}

// no-op launch-slot pad so k_knn lands in the ncu-profiled position (#4)
__global__ void k_nop() { if (threadIdx.x == 1024) g_sink = 1; }

// ---------------------------------------------------------------------------
// K2: per-event exact KNN, WARP-PER-QUERY (warp-select, registers only).
//  - warp-wide top-64 kept SORTED ascending, distributed 2 elems/lane
//    (element e = r*32 + lane); threshold = element 39 (exact 40th best)
//  - seed = candidates 0..63, bitonic sort-64 across the warp
//  - scan: 32 lanes process 32 coalesced candidates/iter; ballot selects the
//    rare passers; each is broadcast and inserted warp-collectively via a
//    shfl shift (12 instr), threshold refreshed immediately (no staleness)
//  - exact 64-bit (flipped-dist, idx) key compare preserves tie-break order
// ---------------------------------------------------------------------------

// flip: monotone encoding of float bits
__device__ __forceinline__ unsigned int flip_bits(unsigned int b)
{
    return b ^ (unsigned int)(((int)b >> 31) | 0x80000000);
}
// unflip: recover float from order-flipped encoding
__device__ __forceinline__ float key_to_dist(unsigned int b)
{
    unsigned int m = (unsigned int)((int)b >> 31);
    b ^= (m & 0x80000000u) | (~m);
    return __uint_as_float(b);
}

// bitonic sort of 64 ull keys distributed 2/lane (elem e = r*32+lane), asc
__device__ __forceinline__ void warp_sort64(ull& b0, ull& b1, int lane)
{
    const unsigned FULL = 0xffffffffu;
#pragma unroll
    for (int k = 2; k <= 64; k <<= 1) {
#pragma unroll
        for (int j = 32; j > 0; j >>= 1) {
            if (j >= k) continue;
            if (j == 32) {
                // partner = other register, same lane; k==64 -> ascending
                ull lo = (b0 < b1) ? b0 : b1;
                ull hi = (b0 < b1) ? b1 : b0;
                b0 = lo; b1 = hi;
            } else {
                ull o0 = __shfl_xor_sync(FULL, b0, j);
                ull o1 = __shfl_xor_sync(FULL, b1, j);
                bool lower = ((lane & j) == 0);
                bool asc0, asc1;
                if (k == 64)      { asc0 = true; asc1 = true; }
                else if (k == 32) { asc0 = true; asc1 = false; }
                else {
                    asc0 = ((lane & k) == 0);
                    asc1 = asc0;
                }
                bool m0 = (lower == asc0);   // take min?
                bool m1 = (lower == asc1);
                b0 = m0 ? (b0 < o0 ? b0 : o0) : (b0 > o0 ? b0 : o0);
                b1 = m1 ? (b1 < o1 ? b1 : o1) : (b1 > o1 ? b1 : o1);
            }
        }
    }
}

// insert key into the distributed sorted-64 list (drops old max)
__device__ __forceinline__ void warp_insert(ull key, ull& b0, ull& b1, int lane)
{
    const unsigned FULL = 0xffffffffu;
    ull p0  = __shfl_up_sync(FULL, b0, 1);   // elem[p-1] for b0 (lane>0)
    ull p1  = __shfl_up_sync(FULL, b1, 1);   // elem[p-1] for b1 (lane>0)
    ull e31 = __shfl_sync(FULL, b0, 31);     // elem 31 (prev of elem 32)
    if (lane == 0) { p0 = 0ull; p1 = e31; }
    // new[p] = old[p] if old[p] <= key; else (old[p-1] > key ? old[p-1] : key)
    b0 = (b0 <= key) ? b0 : (p0 > key ? p0 : key);
    b1 = (b1 <= key) ? b1 : (p1 > key ? p1 : key);
}

#define KNN_WARPS 8   // warps (queries) per block

__global__ __launch_bounds__(KNN_WARPS * 32)
void k_knn(float* __restrict__ nidx_out,   // may be null (float-cast indices)
           float* __restrict__ dist_out)   // may be null
{
    const unsigned FULL = 0xffffffffu;
    int ev     = blockIdx.y;
    int base   = ev * V_EV;
    int warpid = threadIdx.x >> 5;
    int lane   = threadIdx.x & 31;
    int q      = blockIdx.x * KNN_WARPS + warpid;   // V_EV % KNN_WARPS == 0

    const float* px = &g_cx[base];
    const float* py = &g_cy[base];
    const float* pz = &g_cz[base];
    const float* pw = &g_cw[base];
    const float* pn = &g_cn[base];

    float qx = __ldg(px + q);
    float qy = __ldg(py + q);
    float qz = __ldg(pz + q);
    float qw = __ldg(pw + q);
    float qs = __ldg(pn + q);

    // ---- seed: candidates lane and 32+lane -> sorted top-64 ----
    ull b0, b1;
    {
        int i0 = lane, i1 = 32 + lane;
        float dot0 = qx * __ldg(px + i0);
        dot0 = fmaf(qy, __ldg(py + i0), dot0);
        dot0 = fmaf(qz, __ldg(pz + i0), dot0);
        dot0 = fmaf(qw, __ldg(pw + i0), dot0);
        float d0 = fmaf(-2.0f, dot0, qs + __ldg(pn + i0));
        float dot1 = qx * __ldg(px + i1);
        dot1 = fmaf(qy, __ldg(py + i1), dot1);
        dot1 = fmaf(qz, __ldg(pz + i1), dot1);
        dot1 = fmaf(qw, __ldg(pw + i1), dot1);
        float d1 = fmaf(-2.0f, dot1, qs + __ldg(pn + i1));
        b0 = (i0 == q) ? ~0ull
                       : (((ull)flip_bits(__float_as_uint(d0)) << 32) | (unsigned)i0);
        b1 = (i1 == q) ? ~0ull
                       : (((ull)flip_bits(__float_as_uint(d1)) << 32) | (unsigned)i1);
    }
    warp_sort64(b0, b1, lane);

    ull   thrk  = __shfl_sync(FULL, b1, 7);              // element 39
    float thr_f = key_to_dist((unsigned)(thrk >> 32));   // always real (>=63 seeds)

    // ---- scan candidates 64..2999, 32 per iteration, coalesced ----
    for (int it = 2; it < (V_EV + 31) / 32 + ((V_EV & 31) ? 1 : 0) + 0; it++) {
        int idx = it * 32 + lane;
        if (it * 32 >= V_EV) break;
        int cl = (idx < V_EV) ? idx : (V_EV - 1);
        float cx = __ldg(px + cl), cy = __ldg(py + cl);
        float cz = __ldg(pz + cl), cw = __ldg(pw + cl);
        float nn = __ldg(pn + cl);
        float dot = qx * cx;
        dot = fmaf(qy, cy, dot);
        dot = fmaf(qz, cz, dot);
        dot = fmaf(qw, cw, dot);
        float d = fmaf(-2.0f, dot, qs + nn);

        bool pass = (idx < V_EV) && (idx != q) && (d <= thr_f);
        unsigned m = __ballot_sync(FULL, pass);
        while (m) {
            int l = __ffs(m) - 1;
            m &= m - 1;
            unsigned db = __shfl_sync(FULL, __float_as_uint(d), l);
            ull key = ((ull)flip_bits(db) << 32) | (unsigned)(it * 32 + l);
            if (key < thrk) {          // exact (dist, idx) compare
                warp_insert(key, b0, b1, lane);
                thrk  = __shfl_sync(FULL, b1, 7);
                thr_f = key_to_dist((unsigned)(thrk >> 32));
            }
        }
    }

    // ---- output: elements 0..31 = b0, 32..39 = b1 lanes 0..7 ----
    size_t rowoff = (size_t)(base + q) * KNN_K;
    {
        unsigned widx = (unsigned)b0;
        float dd = fmaxf(key_to_dist((unsigned)(b0 >> 32)), 0.0f);
        int gidx = base + (int)widx;
        g_nidx[rowoff + lane] = gidx;
        g_dist[rowoff + lane] = dd;
        if (nidx_out) nidx_out[rowoff + lane] = (float)gidx;
        if (dist_out) dist_out[rowoff + lane] = dd;
    }
    if (lane < KNN_K - 32) {
        unsigned widx = (unsigned)b1;
        float dd = fmaxf(key_to_dist((unsigned)(b1 >> 32)), 0.0f);
        int gidx = base + (int)widx;
        g_nidx[rowoff + 32 + lane] = gidx;
        g_dist[rowoff + 32 + lane] = dd;
        if (nidx_out) nidx_out[rowoff + 32 + lane] = (float)gidx;
        if (dist_out) dist_out[rowoff + 32 + lane] = dd;
    }
}

// ---------------------------------------------------------------------------
// K3: aggregation. a = [mean_k(f_nbr*w)-f, max_k(f_nbr*w)-f, x]  [N,192]
// ---------------------------------------------------------------------------
__global__ __launch_bounds__(256)
void k_agg(const float* __restrict__ x)
{
    __shared__ float wsh[4][KNN_K];
    __shared__ int   nsh[4][KNN_K];
    int h = threadIdx.x >> 6;
    int p = threadIdx.x & 63;
    int hit = blockIdx.x * 4 + h;

    if (hit < NHITS && p < KNN_K) {
        float dd = g_dist[(size_t)hit * KNN_K + p];
        wsh[h][p] = expf(-10.0f * dd);
        nsh[h][p] = g_nidx[(size_t)hit * KNN_K + p];
    }
    __syncthreads();
    if (hit >= NHITS) return;

    float acc = 0.0f;
    float mx = -INFINITY;
#pragma unroll 8
    for (int k = 0; k < KNN_K; k++) {
        float f = g_feat[(size_t)nsh[h][k] * PROP + p];
        float v = f * wsh[h][k];
        acc += v;
        mx = fmaxf(mx, v);
    }
    float fs = g_feat[(size_t)hit * PROP + p];
    float* arow = &g_a[(size_t)hit * AIN];
    arow[p]        = acc / (float)KNN_K - fs;
    arow[PROP + p] = mx - fs;
    arow[2 * PROP + p] = x[hit * FIN + p];
}

// ---------------------------------------------------------------------------
// K4: out = tanh(a @ W_out + b_out), [60000,192] x [192,128].
// ---------------------------------------------------------------------------
#define GM 128
#define GK 16

__global__ __launch_bounds__(256)
void k_gemm(const float* __restrict__ W, const float* __restrict__ bias,
            float* __restrict__ out)
{
    __shared__ float As[GK][GM + 4];
    __shared__ float Bs[GK][FOUT];

    int tid = threadIdx.x;
    int tx = tid & 15;
    int ty = tid >> 4;
    int rowBase = blockIdx.x * GM;

    float acc[8][8];
#pragma unroll
    for (int i = 0; i < 8; i++)
#pragma unroll
        for (int j = 0; j < 8; j++) acc[i][j] = 0.0f;

    for (int kt = 0; kt < AIN; kt += GK) {
#pragma unroll
        for (int l = 0; l < 2; l++) {
            int id = tid + l * 256;
            int r = id >> 2;
            int c4 = (id & 3) * 4;
            int grow = rowBase + r;
            float4 v = make_float4(0.f, 0.f, 0.f, 0.f);
            if (grow < NHITS)
                v = *(const float4*)&g_a[(size_t)grow * AIN + kt + c4];
            As[c4 + 0][r] = v.x;
            As[c4 + 1][r] = v.y;
            As[c4 + 2][r] = v.z;
            As[c4 + 3][r] = v.w;
        }
#pragma unroll
        for (int l = 0; l < 2; l++) {
            int id = tid + l * 256;
            int r = id >> 5;
            int c = (id & 31) * 4;
            *(float4*)&Bs[r][c] = *(const float4*)&W[(size_t)(kt + r) * FOUT + c];
        }
        __syncthreads();

#pragma unroll
        for (int k = 0; k < GK; k++) {
            float4 a0 = *(const float4*)&As[k][ty * 8];
            float4 a1 = *(const float4*)&As[k][ty * 8 + 4];
            float4 b0 = *(const float4*)&Bs[k][tx * 8];
            float4 b1 = *(const float4*)&Bs[k][tx * 8 + 4];
            float a[8] = {a0.x, a0.y, a0.z, a0.w, a1.x, a1.y, a1.z, a1.w};
            float b[8] = {b0.x, b0.y, b0.z, b0.w, b1.x, b1.y, b1.z, b1.w};
#pragma unroll
            for (int i = 0; i < 8; i++)
#pragma unroll
                for (int j = 0; j < 8; j++)
                    acc[i][j] += a[i] * b[j];
        }
        __syncthreads();
    }

    float bv[8];
#pragma unroll
    for (int j = 0; j < 8; j++) bv[j] = bias[tx * 8 + j];

#pragma unroll
    for (int i = 0; i < 8; i++) {
        int grow = rowBase + ty * 8 + i;
        if (grow < NHITS) {
#pragma unroll
            for (int j = 0; j < 8; j++)
                out[(size_t)grow * FOUT + tx * 8 + j] = tanhf(acc[i][j] + bv[j]);
        }
    }
}

// ---------------------------------------------------------------------------
// launch  (k_nop keeps k_knn in the ncu-profiled position #4)
// ---------------------------------------------------------------------------
extern "C" void kernel_launch(void* const* d_in, const int* in_sizes, int n_in,
                              void* d_out, int out_size)
{
    const float* x  = (const float*)d_in[0];
    const float* Wp = (const float*)d_in[2];
    const float* bp = (const float*)d_in[3];
    const float* Ws = (const float*)d_in[4];
    const float* bs = (const float*)d_in[5];
    const float* Wo = (const float*)d_in[6];
    const float* bo = (const float*)d_in[7];

    float* out = (float*)d_out;

    const int full_sz = NHITS * (FOUT + DIM + KNN_K + KNN_K);
    bool full = (out_size == full_sz);
    float* coords_out = full ? out + (size_t)NHITS * FOUT : nullptr;
    float* nidx_out   = full ? coords_out + (size_t)NHITS * DIM : nullptr;
    float* dist_out   = full ? nidx_out + (size_t)NHITS * KNN_K : nullptr;

    k_transform<<<NHITS / 4, 256>>>(x, Wp, bp, Ws, bs, coords_out);
    k_soa<<<(NHITS + 255) / 256, 256>>>();
    k_nop<<<1, 32>>>();
    k_knn<<<dim3(V_EV / KNN_WARPS, B_EV), KNN_WARPS * 32>>>(nidx_out, dist_out);
    k_agg<<<NHITS / 4, 256>>>(x);
    k_gemm<<<(NHITS + GM - 1) / GM, 256>>>(Wo, bo, out);
}